// round 2
// baseline (speedup 1.0000x reference)
#include <cuda_runtime.h>
#include <cuda_bf16.h>

// Problem constants (fixed by the reference: B=16, T=1024, D=1024, O=10)
#define BB 16
#define TT 1024
#define DD 1024
#define OO 10

// Scratch (device globals: allocation-free per harness rules)
__device__ float g_scores[BB * OO * TT];   // [b][o][t]
__device__ float g_wx[BB * OO * TT];       // softmaxed, [b][o][i]

// Packed fp32x2 FMA (Blackwell FFMA2 — only reachable via PTX fma.rn.f32x2)
__device__ __forceinline__ void ffma2(unsigned long long& acc,
                                      unsigned long long a,
                                      unsigned long long b) {
    asm("fma.rn.f32x2 %0, %1, %2, %0;" : "+l"(acc) : "l"(a), "l"(b));
}
__device__ __forceinline__ float f32x2_hsum(unsigned long long v) {
    unsigned int lo = (unsigned int)v, hi = (unsigned int)(v >> 32);
    return __uint_as_float(lo) + __uint_as_float(hi);
}

// ---------------------------------------------------------------------------
// Shared GEMV body: rows x D (.) Wsm[OO][DD]^T, 5 outputs per warp.
// Block = 256 threads = 8 warps = 4 row-groups (4 rows each) x 2 o-halves.
// acc40[r][oo] = f32x2 partial for row (rg*4+r), output (oh*5+oo).
// ---------------------------------------------------------------------------
struct Acc45 { unsigned long long a[4][5]; };

__device__ __forceinline__ Acc45 gemv_body(const float* __restrict__ logits_rows,
                                           const float (&Wsm)[OO][DD],
                                           int lane, int oh) {
    Acc45 A;
    #pragma unroll
    for (int r = 0; r < 4; r++)
        #pragma unroll
        for (int o = 0; o < 5; o++) A.a[r][o] = 0ull;

    #pragma unroll 2
    for (int k = 0; k < DD / 128; k++) {
        const int d0 = k * 128 + lane * 4;
        ulonglong2 lg[4];
        #pragma unroll
        for (int r = 0; r < 4; r++)
            lg[r] = *(const ulonglong2*)&logits_rows[r * DD + d0];
        #pragma unroll
        for (int o = 0; o < 5; o++) {
            const ulonglong2 w2 = *(const ulonglong2*)&Wsm[oh * 5 + o][d0];
            #pragma unroll
            for (int r = 0; r < 4; r++) {
                ffma2(A.a[r][o], lg[r].x, w2.x);
                ffma2(A.a[r][o], lg[r].y, w2.y);
            }
        }
    }
    return A;
}

// Reduce the 20 partials across the warp; lane 0 ends with the sums.
__device__ __forceinline__ void warp_reduce45(Acc45& A, float (&res)[4][5]) {
    #pragma unroll
    for (int r = 0; r < 4; r++)
        #pragma unroll
        for (int o = 0; o < 5; o++) {
            float v = f32x2_hsum(A.a[r][o]);
            #pragma unroll
            for (int s = 16; s > 0; s >>= 1)
                v += __shfl_xor_sync(0xffffffffu, v, s);
            res[r][o] = v;
        }
}

// ---------------------------------------------------------------------------
// Kernel 1: scores[b][o][t] = (logits[b,t,:] . W[o,:] + bias[o]) / OO
// Grid 1024 x 256: block covers 16 rows.
// ---------------------------------------------------------------------------
__global__ __launch_bounds__(256) void k_scores(const float* __restrict__ logits,
                                                const float* __restrict__ W,
                                                const float* __restrict__ bias) {
    __shared__ float Wsm[OO][DD];   // 40 KB
    {
        const float4* Wv = (const float4*)W;
        float4* Ws = (float4*)&Wsm[0][0];
        for (int i = threadIdx.x; i < OO * DD / 4; i += 256)
            Ws[i] = Wv[i];
    }
    __syncthreads();

    const int warp = threadIdx.x >> 5;
    const int lane = threadIdx.x & 31;
    const int rg = warp >> 1;          // row group 0..3
    const int oh = warp & 1;           // o half 0..1
    const int row0 = blockIdx.x * 16 + rg * 4;

    Acc45 A = gemv_body(&logits[(size_t)row0 * DD], Wsm, lane, oh);
    float res[4][5];
    warp_reduce45(A, res);

    if (lane == 0) {
        const int b = row0 / TT;
        const int t0 = row0 % TT;
        #pragma unroll
        for (int r = 0; r < 4; r++)
            #pragma unroll
            for (int o = 0; o < 5; o++) {
                const int oo = oh * 5 + o;
                g_scores[(b * OO + oo) * TT + (t0 + r)] =
                    (res[r][o] + bias[oo]) * (1.0f / OO);
            }
    }
}

// ---------------------------------------------------------------------------
// Kernel 2: softmax over t for each (b,o). 160 blocks x 256 threads.
// ---------------------------------------------------------------------------
__global__ __launch_bounds__(256) void k_softmax() {
    const int ro = blockIdx.x;
    const int tid = threadIdx.x;
    const float4 v = ((const float4*)&g_scores[ro * TT])[tid];

    __shared__ float red[8];

    float m = fmaxf(fmaxf(v.x, v.y), fmaxf(v.z, v.w));
    #pragma unroll
    for (int s = 16; s > 0; s >>= 1)
        m = fmaxf(m, __shfl_xor_sync(0xffffffffu, m, s));
    if ((tid & 31) == 0) red[tid >> 5] = m;
    __syncthreads();
    float mall = red[0];
    #pragma unroll
    for (int i = 1; i < 8; i++) mall = fmaxf(mall, red[i]);
    __syncthreads();

    float4 e;
    e.x = __expf(v.x - mall);
    e.y = __expf(v.y - mall);
    e.z = __expf(v.z - mall);
    e.w = __expf(v.w - mall);
    float s4 = e.x + e.y + e.z + e.w;
    #pragma unroll
    for (int s = 16; s > 0; s >>= 1)
        s4 += __shfl_xor_sync(0xffffffffu, s4, s);
    if ((tid & 31) == 0) red[tid >> 5] = s4;
    __syncthreads();
    float sall = 0.0f;
    #pragma unroll
    for (int i = 0; i < 8; i++) sall += red[i];

    const float inv = 1.0f / sall;
    float4 w;
    w.x = e.x * inv; w.y = e.y * inv; w.z = e.z * inv; w.w = e.w * inv;
    ((float4*)&g_wx[ro * TT])[tid] = w;
}

// ---------------------------------------------------------------------------
// Kernel 3: out[b][o][t] = sum_i logits[b,t,i] * g_wx[b][o][i]
// Same skeleton, per-batch weight from g_wx. 16 rows/block never crosses a
// batch boundary (TT % 16 == 0).
// ---------------------------------------------------------------------------
__global__ __launch_bounds__(256) void k_out(const float* __restrict__ logits,
                                             float* __restrict__ out) {
    __shared__ float Wsm[OO][DD];

    const int row0blk = blockIdx.x * 16;
    const int b = row0blk / TT;
    {
        const float4* Wv = (const float4*)&g_wx[b * OO * TT];
        float4* Ws = (float4*)&Wsm[0][0];
        for (int i = threadIdx.x; i < OO * DD / 4; i += 256)
            Ws[i] = Wv[i];
    }
    __syncthreads();

    const int warp = threadIdx.x >> 5;
    const int lane = threadIdx.x & 31;
    const int rg = warp >> 1;
    const int oh = warp & 1;
    const int row0 = row0blk + rg * 4;

    Acc45 A = gemv_body(&logits[(size_t)row0 * DD], Wsm, lane, oh);
    float res[4][5];
    warp_reduce45(A, res);

    if (lane == 0) {
        const int t0 = row0 % TT;
        #pragma unroll
        for (int r = 0; r < 4; r++)
            #pragma unroll
            for (int o = 0; o < 5; o++) {
                const int oo = oh * 5 + o;
                out[(b * OO + oo) * TT + (t0 + r)] = res[r][o];
            }
    }
}

// ---------------------------------------------------------------------------
// Launch: inputs per metadata order: logits, decision(unused), W, b
// ---------------------------------------------------------------------------
extern "C" void kernel_launch(void* const* d_in, const int* in_sizes, int n_in,
                              void* d_out, int out_size) {
    const float* logits = (const float*)d_in[0];
    const float* W = (const float*)d_in[2];
    const float* bias = (const float*)d_in[3];
    float* out = (float*)d_out;

    k_scores<<<(BB * TT) / 16, 256>>>(logits, W, bias);
    k_softmax<<<BB * OO, 256>>>();
    k_out<<<(BB * TT) / 16, 256>>>(logits, out);
}